// round 1
// baseline (speedup 1.0000x reference)
#include <cuda_runtime.h>

#define L_TOK 3120
#define DIM 1536
#define NH 12
#define HD 128
#define FR 1560
#define SCALE_F 0.08838834764831845f

// ---------------- scratch (no allocations allowed) ----------------
__device__ float g_q[L_TOK * DIM];
__device__ float g_k[L_TOK * DIM];
__device__ float g_v[L_TOK * DIM];
__device__ float g_a[L_TOK * DIM];

// ---------------- GEMM: C[M,N] = A[M,K] @ W[K,N] + bias ----------------
// 128x128 block tile, BK=8, 256 threads, 8x8 per thread.
__global__ __launch_bounds__(256) void gemm_bias_kernel(
    const float* __restrict__ A, const float* __restrict__ W,
    const float* __restrict__ bias, float* __restrict__ C,
    int M, int N, int K) {
  __shared__ float As[8][128];
  __shared__ float Bs[8][128];

  const int t = threadIdx.x;
  const int m0 = blockIdx.y * 128;
  const int n0 = blockIdx.x * 128;
  const int ty = t >> 4;        // 0..15
  const int tx = t & 15;        // 0..15

  const int arow = t >> 1;            // 0..127
  const int ak   = (t & 1) * 4;       // 0 or 4
  const int brow = t >> 5;            // 0..7
  const int bcol = (t & 31) * 4;      // 0..124

  const bool aval = (m0 + arow) < M;
  const float* Ap = A + (size_t)(m0 + arow) * K + ak;
  const float* Wp = W + (size_t)brow * N + n0 + bcol;

  float acc[8][8];
#pragma unroll
  for (int i = 0; i < 8; i++)
#pragma unroll
    for (int j = 0; j < 8; j++) acc[i][j] = 0.f;

  for (int k0 = 0; k0 < K; k0 += 8) {
    float4 av = make_float4(0.f, 0.f, 0.f, 0.f);
    if (aval) av = *(const float4*)(Ap + k0);
    As[ak + 0][arow] = av.x;
    As[ak + 1][arow] = av.y;
    As[ak + 2][arow] = av.z;
    As[ak + 3][arow] = av.w;
    float4 bv = *(const float4*)(Wp + (size_t)k0 * N);
    *(float4*)&Bs[brow][bcol] = bv;
    __syncthreads();

#pragma unroll
    for (int kk = 0; kk < 8; kk++) {
      float4 a0 = *(const float4*)&As[kk][ty * 8];
      float4 a1 = *(const float4*)&As[kk][ty * 8 + 4];
      float4 b0 = *(const float4*)&Bs[kk][tx * 8];
      float4 b1 = *(const float4*)&Bs[kk][tx * 8 + 4];
      float a[8] = {a0.x, a0.y, a0.z, a0.w, a1.x, a1.y, a1.z, a1.w};
      float b[8] = {b0.x, b0.y, b0.z, b0.w, b1.x, b1.y, b1.z, b1.w};
#pragma unroll
      for (int i = 0; i < 8; i++)
#pragma unroll
        for (int j = 0; j < 8; j++) acc[i][j] += a[i] * b[j];
    }
    __syncthreads();
  }

#pragma unroll
  for (int i = 0; i < 8; i++) {
    int row = m0 + ty * 8 + i;
    if (row >= M) continue;
    float* Cp = C + (size_t)row * N + n0 + tx * 8;
    const float* bp = bias + n0 + tx * 8;
    float4 o0 = make_float4(acc[i][0] + bp[0], acc[i][1] + bp[1],
                            acc[i][2] + bp[2], acc[i][3] + bp[3]);
    float4 o1 = make_float4(acc[i][4] + bp[4], acc[i][5] + bp[5],
                            acc[i][6] + bp[6], acc[i][7] + bp[7]);
    *(float4*)Cp = o0;
    *(float4*)(Cp + 4) = o1;
  }
}

// ---------------- fused RMSNorm + RoPE (in-place on q/k) ----------------
__global__ __launch_bounds__(256) void rms_rope_kernel(
    float* __restrict__ qbuf, float* __restrict__ kbuf,
    const float* __restrict__ gq, const float* __restrict__ gk,
    const float* __restrict__ cosp, const float* __restrict__ sinp) {
  const int l = blockIdx.x;
  float* row = (blockIdx.y == 0) ? (qbuf + (size_t)l * DIM) : (kbuf + (size_t)l * DIM);
  const float* g = (blockIdx.y == 0) ? gq : gk;
  const int t = threadIdx.x;

  float2 v[3];
  float ss = 0.f;
#pragma unroll
  for (int j = 0; j < 3; j++) {
    int p = t + 256 * j;                 // pair index 0..767
    v[j] = ((const float2*)row)[p];
    ss += v[j].x * v[j].x + v[j].y * v[j].y;
  }
#pragma unroll
  for (int off = 16; off > 0; off >>= 1)
    ss += __shfl_xor_sync(0xffffffffu, ss, off);
  __shared__ float red[8];
  if ((t & 31) == 0) red[t >> 5] = ss;
  __syncthreads();
  float tot = 0.f;
#pragma unroll
  for (int w = 0; w < 8; w++) tot += red[w];
  const float r = rsqrtf(tot * (1.0f / (float)DIM) + 1e-6f);

#pragma unroll
  for (int j = 0; j < 3; j++) {
    int p = t + 256 * j;
    int hd2 = p & 63;                    // pair index within head
    float c = cosp[l * 64 + hd2];
    float s = sinp[l * 64 + hd2];
    float e = v[j].x * r * g[2 * p];
    float o = v[j].y * r * g[2 * p + 1];
    float2 outp;
    outp.x = e * c - o * s;
    outp.y = e * s + o * c;
    ((float2*)row)[p] = outp;
  }
}

// ---------------- flash attention (fp32, frame-causal) ----------------
#define BQ 64
#define BKV 64
#define KVS 132                 // KV smem row stride (floats), 16B-aligned, conflict-free
#define SST 65                  // S smem row stride
#define ATTN_SMEM ((64 * 128 + 64 * KVS + 64 * SST + 192) * 4)

__global__ __launch_bounds__(256, 2) void attn_kernel(
    const float* __restrict__ q, const float* __restrict__ k,
    const float* __restrict__ v, float* __restrict__ o) {
  extern __shared__ float sm[];
  float* Qs  = sm;                       // [64][128]
  float* KVs = sm + 64 * 128;            // [64][132]  (K, then reused for V)
  float* Ss  = KVs + 64 * KVS;           // [64][65]
  float* m_s = Ss + 64 * SST;            // [64]
  float* l_s = m_s + 64;                 // [64]
  float* c_s = l_s + 64;                 // [64]

  const int t = threadIdx.x;
  const int q0 = blockIdx.x * BQ;
  const int h = blockIdx.y;

  // load Q tile (zero-fill past L)
#pragma unroll
  for (int i = 0; i < 8; i++) {
    int idx = t + 256 * i;
    int r = idx >> 5, c4 = (idx & 31) << 2;
    int qr = q0 + r;
    float4 val = make_float4(0.f, 0.f, 0.f, 0.f);
    if (qr < L_TOK) val = *(const float4*)(q + (size_t)qr * DIM + h * HD + c4);
    *(float4*)(Qs + r * 128 + c4) = val;
  }
  if (t < 64) { m_s[t] = -3.0e38f; l_s[t] = 0.f; }

  // PV / output mapping: 4 rows x 8 cols per thread
  const int rg = t >> 4;                 // 0..15 -> rows rg*4..rg*4+3
  const int cg = t & 15;                 // 0..15 -> cols cg*8..cg*8+7
  float acc[4][8];
#pragma unroll
  for (int i = 0; i < 4; i++)
#pragma unroll
    for (int j = 0; j < 8; j++) acc[i][j] = 0.f;

  // S mapping: one key-col per thread, 16 query rows
  const int sc = t & 63;
  const int sr0 = (t >> 6) << 4;
  // softmax mapping: 4 threads per row
  const int xr = t >> 2, xs = t & 3;

  int qlast = q0 + BQ - 1;
  if (qlast >= L_TOK) qlast = L_TOK - 1;
  const int kmax_all = (qlast < FR) ? FR : L_TOK;     // F=2: limit is 1560 or 3120
  const int ntiles = (kmax_all + BKV - 1) / BKV;

  for (int kt = 0; kt < ntiles; kt++) {
    const int kb = kt * BKV;
    __syncthreads();
    // K tile
#pragma unroll
    for (int i = 0; i < 8; i++) {
      int idx = t + 256 * i;
      int r = idx >> 5, c4 = (idx & 31) << 2;
      int kr = kb + r;
      float4 val = make_float4(0.f, 0.f, 0.f, 0.f);
      if (kr < L_TOK) val = *(const float4*)(k + (size_t)kr * DIM + h * HD + c4);
      *(float4*)(KVs + r * KVS + c4) = val;
    }
    __syncthreads();

    // S = Q K^T  (Q reads are warp-broadcast LDS.128; K reads conflict-free w/ stride 132)
    float sacc[16];
#pragma unroll
    for (int i = 0; i < 16; i++) sacc[i] = 0.f;
#pragma unroll 2
    for (int kd = 0; kd < 32; kd++) {
      float4 kv = *(const float4*)(KVs + sc * KVS + kd * 4);
#pragma unroll
      for (int i = 0; i < 16; i++) {
        float4 qv = *(const float4*)(Qs + (sr0 + i) * 128 + kd * 4);
        sacc[i] += qv.x * kv.x + qv.y * kv.y + qv.z * kv.z + qv.w * kv.w;
      }
    }
    const int kg = kb + sc;
#pragma unroll
    for (int i = 0; i < 16; i++) {
      int qrow = q0 + sr0 + i;
      int km = (qrow < FR) ? FR : L_TOK;               // frame-causal limit
      Ss[(sr0 + i) * SST + sc] = (kg < km) ? sacc[i] * SCALE_F : -3.0e38f;
    }
    __syncthreads();

    // V tile load (KVs free: S-compute done) + online softmax on Ss
#pragma unroll
    for (int i = 0; i < 8; i++) {
      int idx = t + 256 * i;
      int r = idx >> 5, c4 = (idx & 31) << 2;
      int kr = kb + r;
      float4 val = make_float4(0.f, 0.f, 0.f, 0.f);
      if (kr < L_TOK) val = *(const float4*)(v + (size_t)kr * DIM + h * HD + c4);
      *(float4*)(KVs + r * KVS + c4) = val;
    }
    {
      float sv[16];
      float mloc = -3.0e38f;
#pragma unroll
      for (int i = 0; i < 16; i++) {
        sv[i] = Ss[xr * SST + xs * 16 + i];
        mloc = fmaxf(mloc, sv[i]);
      }
      mloc = fmaxf(mloc, __shfl_xor_sync(0xffffffffu, mloc, 1));
      mloc = fmaxf(mloc, __shfl_xor_sync(0xffffffffu, mloc, 2));
      float mold = m_s[xr];
      float mnew = fmaxf(mold, mloc);
      float corr = __expf(mold - mnew);
      float lsum = 0.f;
#pragma unroll
      for (int i = 0; i < 16; i++) {
        float p = __expf(sv[i] - mnew);
        lsum += p;
        Ss[xr * SST + xs * 16 + i] = p;
      }
      lsum += __shfl_xor_sync(0xffffffffu, lsum, 1);
      lsum += __shfl_xor_sync(0xffffffffu, lsum, 2);
      if (xs == 0) {
        m_s[xr] = mnew;
        l_s[xr] = l_s[xr] * corr + lsum;
        c_s[xr] = corr;
      }
    }
    __syncthreads();

    // O = corr*O + P @ V
    float cr[4];
#pragma unroll
    for (int i = 0; i < 4; i++) cr[i] = c_s[rg * 4 + i];
#pragma unroll
    for (int i = 0; i < 4; i++)
#pragma unroll
      for (int j = 0; j < 8; j++) acc[i][j] *= cr[i];
#pragma unroll 8
    for (int kk = 0; kk < BKV; kk++) {
      float4 v0 = *(const float4*)(KVs + kk * KVS + cg * 8);
      float4 v1 = *(const float4*)(KVs + kk * KVS + cg * 8 + 4);
#pragma unroll
      for (int i = 0; i < 4; i++) {
        float p = Ss[(rg * 4 + i) * SST + kk];
        acc[i][0] += p * v0.x; acc[i][1] += p * v0.y;
        acc[i][2] += p * v0.z; acc[i][3] += p * v0.w;
        acc[i][4] += p * v1.x; acc[i][5] += p * v1.y;
        acc[i][6] += p * v1.z; acc[i][7] += p * v1.w;
      }
    }
  }
  __syncthreads();

#pragma unroll
  for (int i = 0; i < 4; i++) {
    int qr = q0 + rg * 4 + i;
    if (qr < L_TOK) {
      float inv = 1.0f / l_s[rg * 4 + i];
      float4 o0 = make_float4(acc[i][0] * inv, acc[i][1] * inv,
                              acc[i][2] * inv, acc[i][3] * inv);
      float4 o1 = make_float4(acc[i][4] * inv, acc[i][5] * inv,
                              acc[i][6] * inv, acc[i][7] * inv);
      *(float4*)(o + (size_t)qr * DIM + h * HD + cg * 8) = o0;
      *(float4*)(o + (size_t)qr * DIM + h * HD + cg * 8 + 4) = o1;
    }
  }
}

// ---------------- launch ----------------
extern "C" void kernel_launch(void* const* d_in, const int* in_sizes, int n_in,
                              void* d_out, int out_size) {
  const float* x  = (const float*)d_in[0];
  const float* wq = (const float*)d_in[1];
  const float* wk = (const float*)d_in[2];
  const float* wv = (const float*)d_in[3];
  const float* wo = (const float*)d_in[4];
  const float* bq = (const float*)d_in[5];
  const float* bk = (const float*)d_in[6];
  const float* bv = (const float*)d_in[7];
  const float* bo = (const float*)d_in[8];
  const float* gq = (const float*)d_in[9];
  const float* gk = (const float*)d_in[10];
  const float* fc = (const float*)d_in[11];
  const float* fs = (const float*)d_in[12];
  float* out = (float*)d_out;

  float *qb, *kb, *vb, *ab;
  cudaGetSymbolAddress((void**)&qb, g_q);
  cudaGetSymbolAddress((void**)&kb, g_k);
  cudaGetSymbolAddress((void**)&vb, g_v);
  cudaGetSymbolAddress((void**)&ab, g_a);

  dim3 gg(DIM / 128, (L_TOK + 127) / 128);   // (12, 25)
  gemm_bias_kernel<<<gg, 256>>>(x, wq, bq, qb, L_TOK, DIM, DIM);
  gemm_bias_kernel<<<gg, 256>>>(x, wk, bk, kb, L_TOK, DIM, DIM);
  gemm_bias_kernel<<<gg, 256>>>(x, wv, bv, vb, L_TOK, DIM, DIM);

  rms_rope_kernel<<<dim3(L_TOK, 2), 256>>>(qb, kb, gq, gk, fc, fs);

  cudaFuncSetAttribute(attn_kernel, cudaFuncAttributeMaxDynamicSharedMemorySize,
                       ATTN_SMEM);
  attn_kernel<<<dim3((L_TOK + BQ - 1) / BQ, NH), 256, ATTN_SMEM>>>(qb, kb, vb, ab);

  gemm_bias_kernel<<<gg, 256>>>(ab, wo, bo, out, L_TOK, DIM, DIM);
}

// round 2
// speedup vs baseline: 1.3676x; 1.3676x over previous
#include <cuda_runtime.h>

#define L_TOK 3120
#define DIM 1536
#define NH 12
#define HD 128
#define FR 1560
#define SCALE_F 0.08838834764831845f

// ---------------- scratch (no allocations allowed) ----------------
__device__ float g_q[L_TOK * DIM];
__device__ float g_k[L_TOK * DIM];
__device__ float g_v[L_TOK * DIM];
__device__ float g_a[L_TOK * DIM];

// ---------------- tf32 helpers ----------------
__device__ __forceinline__ unsigned f2tf32(float x) {
  unsigned r;
  asm("cvt.rna.tf32.f32 %0, %1;" : "=r"(r) : "f"(x));
  return r;
}

__device__ __forceinline__ void mma_tf32(float c[4], const unsigned a[4],
                                         const unsigned b[2]) {
  asm volatile(
      "mma.sync.aligned.m16n8k8.row.col.f32.tf32.tf32.f32 "
      "{%0,%1,%2,%3},{%4,%5,%6,%7},{%8,%9},{%0,%1,%2,%3};"
      : "+f"(c[0]), "+f"(c[1]), "+f"(c[2]), "+f"(c[3])
      : "r"(a[0]), "r"(a[1]), "r"(a[2]), "r"(a[3]), "r"(b[0]), "r"(b[1]));
}

// ---------------- GEMM via tf32 tensor cores ----------------
// C[M,N] = A[M,K] @ W[K,N] + bias. CTA tile 128x128, BK=32, 256 thr (8 warps),
// warp tile 32x64 (2 m-atoms x 8 n-atoms of m16n8k8). cp.async double buffer.
#define BM 128
#define BN 128
#define BK 32
#define AST 36   // As stride (floats): bank(m,k) = (4m+k)%32 -> conflict-free frags
#define BST 136  // Bs stride: bank(k,n) = (8k+n)%32 -> conflict-free frags
#define GEMM_SMEM ((2 * (BM * AST + BK * BST)) * 4)

__global__ __launch_bounds__(256) void gemm_tc_kernel(
    const float* __restrict__ A, const float* __restrict__ W,
    const float* __restrict__ bias, float* __restrict__ C,
    int M, int N, int K) {
  extern __shared__ float smn[];
  float* As = smn;                    // [2][BM][AST]  layout [m][k]
  float* Bs = smn + 2 * BM * AST;     // [2][BK][BST]  layout [k][n]

  const int t = threadIdx.x;
  const int m0 = blockIdx.y * BM;
  const int n0 = blockIdx.x * BN;

  const int warp = t >> 5, lane = t & 31;
  const int wm = (warp & 3) * 32;   // 4 warps along M
  const int wn = (warp >> 2) * 64;  // 2 warps along N
  const int g = lane >> 2, t4 = lane & 3;

  float c[2][8][4];
#pragma unroll
  for (int i = 0; i < 2; i++)
#pragma unroll
    for (int j = 0; j < 8; j++)
#pragma unroll
      for (int r = 0; r < 4; r++) c[i][j][r] = 0.f;

  // ---- prefetch helper (cp.async, 16B each) ----
  auto prefetch = [&](int buf, int k0) {
    float* asb = As + buf * BM * AST;
    float* bsb = Bs + buf * BK * BST;
#pragma unroll
    for (int i = 0; i < 4; i++) {
      int idx = t + 256 * i;                  // 1024 float4s for A tile
      int row = idx >> 3, c4 = (idx & 7) << 2;
      int gr = m0 + row;
      if (gr >= M) gr = M - 1;                // clamp: junk rows masked at store
      unsigned dst = (unsigned)__cvta_generic_to_shared(asb + row * AST + c4);
      asm volatile("cp.async.cg.shared.global [%0], [%1], 16;" ::"r"(dst),
                   "l"(A + (size_t)gr * K + k0 + c4));
    }
#pragma unroll
    for (int i = 0; i < 4; i++) {
      int idx = t + 256 * i;                  // 1024 float4s for B tile
      int row = idx >> 5, c4 = (idx & 31) << 2;
      unsigned dst = (unsigned)__cvta_generic_to_shared(bsb + row * BST + c4);
      asm volatile("cp.async.cg.shared.global [%0], [%1], 16;" ::"r"(dst),
                   "l"(W + (size_t)(k0 + row) * N + n0 + c4));
    }
  };

  prefetch(0, 0);
  asm volatile("cp.async.commit_group;");

  const int KT = K / BK;
  for (int kt = 0; kt < KT; kt++) {
    const int buf = kt & 1;
    if (kt + 1 < KT) prefetch(buf ^ 1, (kt + 1) * BK);
    asm volatile("cp.async.commit_group;");
    asm volatile("cp.async.wait_group 1;");
    __syncthreads();

    const float* asb = As + buf * BM * AST;
    const float* bsb = Bs + buf * BK * BST;

#pragma unroll
    for (int ka = 0; ka < 4; ka++) {
      const int kk = ka * 8;
      unsigned av[2][4], bv[8][2];
#pragma unroll
      for (int am = 0; am < 2; am++) {
        const int r = wm + 16 * am + g;
        av[am][0] = f2tf32(asb[r * AST + kk + t4]);
        av[am][1] = f2tf32(asb[(r + 8) * AST + kk + t4]);
        av[am][2] = f2tf32(asb[r * AST + kk + t4 + 4]);
        av[am][3] = f2tf32(asb[(r + 8) * AST + kk + t4 + 4]);
      }
#pragma unroll
      for (int an = 0; an < 8; an++) {
        const int cn = wn + 8 * an + g;
        bv[an][0] = f2tf32(bsb[(kk + t4) * BST + cn]);
        bv[an][1] = f2tf32(bsb[(kk + t4 + 4) * BST + cn]);
      }
#pragma unroll
      for (int am = 0; am < 2; am++)
#pragma unroll
        for (int an = 0; an < 8; an++) mma_tf32(c[am][an], av[am], bv[an]);
    }
    __syncthreads();
  }

  // ---- epilogue: += bias, write float2 pairs ----
#pragma unroll
  for (int am = 0; am < 2; am++) {
    const int r0 = m0 + wm + 16 * am + g;
    const int r1 = r0 + 8;
#pragma unroll
    for (int an = 0; an < 8; an++) {
      const int col = n0 + wn + 8 * an + 2 * t4;
      const float b0 = bias[col], b1 = bias[col + 1];
      if (r0 < M) {
        float2 v0 = make_float2(c[am][an][0] + b0, c[am][an][1] + b1);
        *(float2*)(C + (size_t)r0 * N + col) = v0;
      }
      if (r1 < M) {
        float2 v1 = make_float2(c[am][an][2] + b0, c[am][an][3] + b1);
        *(float2*)(C + (size_t)r1 * N + col) = v1;
      }
    }
  }
}

// ---------------- fused RMSNorm + RoPE (in-place on q/k) ----------------
__global__ __launch_bounds__(256) void rms_rope_kernel(
    float* __restrict__ qbuf, float* __restrict__ kbuf,
    const float* __restrict__ gq, const float* __restrict__ gk,
    const float* __restrict__ cosp, const float* __restrict__ sinp) {
  const int l = blockIdx.x;
  float* row = (blockIdx.y == 0) ? (qbuf + (size_t)l * DIM) : (kbuf + (size_t)l * DIM);
  const float* g = (blockIdx.y == 0) ? gq : gk;
  const int t = threadIdx.x;

  float2 v[3];
  float ss = 0.f;
#pragma unroll
  for (int j = 0; j < 3; j++) {
    int p = t + 256 * j;
    v[j] = ((const float2*)row)[p];
    ss += v[j].x * v[j].x + v[j].y * v[j].y;
  }
#pragma unroll
  for (int off = 16; off > 0; off >>= 1)
    ss += __shfl_xor_sync(0xffffffffu, ss, off);
  __shared__ float red[8];
  if ((t & 31) == 0) red[t >> 5] = ss;
  __syncthreads();
  float tot = 0.f;
#pragma unroll
  for (int w = 0; w < 8; w++) tot += red[w];
  const float r = rsqrtf(tot * (1.0f / (float)DIM) + 1e-6f);

#pragma unroll
  for (int j = 0; j < 3; j++) {
    int p = t + 256 * j;
    int hd2 = p & 63;
    float cth = cosp[l * 64 + hd2];
    float sth = sinp[l * 64 + hd2];
    float e = v[j].x * r * g[2 * p];
    float o = v[j].y * r * g[2 * p + 1];
    float2 outp;
    outp.x = e * cth - o * sth;
    outp.y = e * sth + o * cth;
    ((float2*)row)[p] = outp;
  }
}

// ---------------- flash attention (fp32, frame-causal) ----------------
#define BQ 64
#define BKV 64
#define KVS 132
#define SST 65
#define ATTN_SMEM ((64 * 128 + 64 * KVS + 64 * SST + 192) * 4)

__global__ __launch_bounds__(256, 2) void attn_kernel(
    const float* __restrict__ q, const float* __restrict__ k,
    const float* __restrict__ v, float* __restrict__ o) {
  extern __shared__ float sm[];
  float* Qs  = sm;
  float* KVs = sm + 64 * 128;
  float* Ss  = KVs + 64 * KVS;
  float* m_s = Ss + 64 * SST;
  float* l_s = m_s + 64;
  float* c_s = l_s + 64;

  const int t = threadIdx.x;
  const int q0 = blockIdx.x * BQ;
  const int h = blockIdx.y;

#pragma unroll
  for (int i = 0; i < 8; i++) {
    int idx = t + 256 * i;
    int r = idx >> 5, c4 = (idx & 31) << 2;
    int qr = q0 + r;
    float4 val = make_float4(0.f, 0.f, 0.f, 0.f);
    if (qr < L_TOK) val = *(const float4*)(q + (size_t)qr * DIM + h * HD + c4);
    *(float4*)(Qs + r * 128 + c4) = val;
  }
  if (t < 64) { m_s[t] = -3.0e38f; l_s[t] = 0.f; }

  const int rg = t >> 4;
  const int cg = t & 15;
  float acc[4][8];
#pragma unroll
  for (int i = 0; i < 4; i++)
#pragma unroll
    for (int j = 0; j < 8; j++) acc[i][j] = 0.f;

  const int sc = t & 63;
  const int sr0 = (t >> 6) << 4;
  const int xr = t >> 2, xs = t & 3;

  int qlast = q0 + BQ - 1;
  if (qlast >= L_TOK) qlast = L_TOK - 1;
  const int kmax_all = (qlast < FR) ? FR : L_TOK;
  const int ntiles = (kmax_all + BKV - 1) / BKV;

  for (int kt = 0; kt < ntiles; kt++) {
    const int kb = kt * BKV;
    __syncthreads();
#pragma unroll
    for (int i = 0; i < 8; i++) {
      int idx = t + 256 * i;
      int r = idx >> 5, c4 = (idx & 31) << 2;
      int kr = kb + r;
      float4 val = make_float4(0.f, 0.f, 0.f, 0.f);
      if (kr < L_TOK) val = *(const float4*)(k + (size_t)kr * DIM + h * HD + c4);
      *(float4*)(KVs + r * KVS + c4) = val;
    }
    __syncthreads();

    float sacc[16];
#pragma unroll
    for (int i = 0; i < 16; i++) sacc[i] = 0.f;
#pragma unroll 2
    for (int kd = 0; kd < 32; kd++) {
      float4 kv = *(const float4*)(KVs + sc * KVS + kd * 4);
#pragma unroll
      for (int i = 0; i < 16; i++) {
        float4 qv = *(const float4*)(Qs + (sr0 + i) * 128 + kd * 4);
        sacc[i] += qv.x * kv.x + qv.y * kv.y + qv.z * kv.z + qv.w * kv.w;
      }
    }
    const int kg = kb + sc;
#pragma unroll
    for (int i = 0; i < 16; i++) {
      int qrow = q0 + sr0 + i;
      int km = (qrow < FR) ? FR : L_TOK;
      Ss[(sr0 + i) * SST + sc] = (kg < km) ? sacc[i] * SCALE_F : -3.0e38f;
    }
    __syncthreads();

#pragma unroll
    for (int i = 0; i < 8; i++) {
      int idx = t + 256 * i;
      int r = idx >> 5, c4 = (idx & 31) << 2;
      int kr = kb + r;
      float4 val = make_float4(0.f, 0.f, 0.f, 0.f);
      if (kr < L_TOK) val = *(const float4*)(v + (size_t)kr * DIM + h * HD + c4);
      *(float4*)(KVs + r * KVS + c4) = val;
    }
    {
      float sv[16];
      float mloc = -3.0e38f;
#pragma unroll
      for (int i = 0; i < 16; i++) {
        sv[i] = Ss[xr * SST + xs * 16 + i];
        mloc = fmaxf(mloc, sv[i]);
      }
      mloc = fmaxf(mloc, __shfl_xor_sync(0xffffffffu, mloc, 1));
      mloc = fmaxf(mloc, __shfl_xor_sync(0xffffffffu, mloc, 2));
      float mold = m_s[xr];
      float mnew = fmaxf(mold, mloc);
      float corr = __expf(mold - mnew);
      float lsum = 0.f;
#pragma unroll
      for (int i = 0; i < 16; i++) {
        float p = __expf(sv[i] - mnew);
        lsum += p;
        Ss[xr * SST + xs * 16 + i] = p;
      }
      lsum += __shfl_xor_sync(0xffffffffu, lsum, 1);
      lsum += __shfl_xor_sync(0xffffffffu, lsum, 2);
      if (xs == 0) {
        m_s[xr] = mnew;
        l_s[xr] = l_s[xr] * corr + lsum;
        c_s[xr] = corr;
      }
    }
    __syncthreads();

    float cr[4];
#pragma unroll
    for (int i = 0; i < 4; i++) cr[i] = c_s[rg * 4 + i];
#pragma unroll
    for (int i = 0; i < 4; i++)
#pragma unroll
      for (int j = 0; j < 8; j++) acc[i][j] *= cr[i];
#pragma unroll 8
    for (int kk = 0; kk < BKV; kk++) {
      float4 v0 = *(const float4*)(KVs + kk * KVS + cg * 8);
      float4 v1 = *(const float4*)(KVs + kk * KVS + cg * 8 + 4);
#pragma unroll
      for (int i = 0; i < 4; i++) {
        float p = Ss[(rg * 4 + i) * SST + kk];
        acc[i][0] += p * v0.x; acc[i][1] += p * v0.y;
        acc[i][2] += p * v0.z; acc[i][3] += p * v0.w;
        acc[i][4] += p * v1.x; acc[i][5] += p * v1.y;
        acc[i][6] += p * v1.z; acc[i][7] += p * v1.w;
      }
    }
  }
  __syncthreads();

#pragma unroll
  for (int i = 0; i < 4; i++) {
    int qr = q0 + rg * 4 + i;
    if (qr < L_TOK) {
      float inv = 1.0f / l_s[rg * 4 + i];
      float4 o0 = make_float4(acc[i][0] * inv, acc[i][1] * inv,
                              acc[i][2] * inv, acc[i][3] * inv);
      float4 o1 = make_float4(acc[i][4] * inv, acc[i][5] * inv,
                              acc[i][6] * inv, acc[i][7] * inv);
      *(float4*)(o + (size_t)qr * DIM + h * HD + cg * 8) = o0;
      *(float4*)(o + (size_t)qr * DIM + h * HD + cg * 8 + 4) = o1;
    }
  }
}

// ---------------- launch ----------------
extern "C" void kernel_launch(void* const* d_in, const int* in_sizes, int n_in,
                              void* d_out, int out_size) {
  const float* x  = (const float*)d_in[0];
  const float* wq = (const float*)d_in[1];
  const float* wk = (const float*)d_in[2];
  const float* wv = (const float*)d_in[3];
  const float* wo = (const float*)d_in[4];
  const float* bq = (const float*)d_in[5];
  const float* bk = (const float*)d_in[6];
  const float* bv = (const float*)d_in[7];
  const float* bo = (const float*)d_in[8];
  const float* gq = (const float*)d_in[9];
  const float* gk = (const float*)d_in[10];
  const float* fc = (const float*)d_in[11];
  const float* fs = (const float*)d_in[12];
  float* out = (float*)d_out;

  float *qb, *kb, *vb, *ab;
  cudaGetSymbolAddress((void**)&qb, g_q);
  cudaGetSymbolAddress((void**)&kb, g_k);
  cudaGetSymbolAddress((void**)&vb, g_v);
  cudaGetSymbolAddress((void**)&ab, g_a);

  cudaFuncSetAttribute(gemm_tc_kernel, cudaFuncAttributeMaxDynamicSharedMemorySize,
                       GEMM_SMEM);

  dim3 gg(DIM / 128, (L_TOK + 127) / 128);   // (12, 25)
  gemm_tc_kernel<<<gg, 256, GEMM_SMEM>>>(x, wq, bq, qb, L_TOK, DIM, DIM);
  gemm_tc_kernel<<<gg, 256, GEMM_SMEM>>>(x, wk, bk, kb, L_TOK, DIM, DIM);
  gemm_tc_kernel<<<gg, 256, GEMM_SMEM>>>(x, wv, bv, vb, L_TOK, DIM, DIM);

  rms_rope_kernel<<<dim3(L_TOK, 2), 256>>>(qb, kb, gq, gk, fc, fs);

  cudaFuncSetAttribute(attn_kernel, cudaFuncAttributeMaxDynamicSharedMemorySize,
                       ATTN_SMEM);
  attn_kernel<<<dim3((L_TOK + BQ - 1) / BQ, NH), 256, ATTN_SMEM>>>(qb, kb, vb, ab);

  gemm_tc_kernel<<<gg, 256, GEMM_SMEM>>>(ab, wo, bo, out, L_TOK, DIM, DIM);
}

// round 3
// speedup vs baseline: 3.6137x; 2.6425x over previous
#include <cuda_runtime.h>

#define L_TOK 3120
#define DIM 1536
#define NH 12
#define HD 128
#define FR 1560
#define SCALE_F 0.08838834764831845f

// ---------------- scratch ----------------
__device__ float g_q[L_TOK * DIM];          // Q: fp32 from GEMM, then tf32+k-perm after rms_rope
__device__ float g_k[L_TOK * DIM];
__device__ float g_v[L_TOK * DIM];          // V^T: [DIM][L_TOK], j-permuted, tf32
__device__ float g_a[L_TOK * DIM];          // attention out, tf32
__device__ float g_xt[L_TOK * DIM];         // x rounded to tf32
__device__ float g_wt[4][DIM * DIM];        // weights rounded to tf32

// ---------------- tf32 helpers ----------------
__device__ __forceinline__ unsigned f2tf32(float x) {
  unsigned r; asm("cvt.rna.tf32.f32 %0, %1;" : "=r"(r) : "f"(x)); return r;
}
__device__ __forceinline__ float rnd_tf32(float x) {
  return __uint_as_float(f2tf32(x));
}
__device__ __forceinline__ void mma_tf32(float c[4], const unsigned a[4],
                                         const unsigned b[2]) {
  asm volatile(
      "mma.sync.aligned.m16n8k8.row.col.f32.tf32.tf32.f32 "
      "{%0,%1,%2,%3},{%4,%5,%6,%7},{%8,%9},{%0,%1,%2,%3};"
      : "+f"(c[0]), "+f"(c[1]), "+f"(c[2]), "+f"(c[3])
      : "r"(a[0]), "r"(a[1]), "r"(a[2]), "r"(a[3]), "r"(b[0]), "r"(b[1]));
}
// within-8-group storage permutation: logical m -> pos (pairs (t,t+4) adjacent)
__device__ __forceinline__ int perm8(int m) { return (m < 4) ? 2 * m : 2 * m - 7; }

// ---------------- tf32 rounding kernel ----------------
__global__ __launch_bounds__(256) void cvt_kernel(const float* __restrict__ s,
                                                  float* __restrict__ d, int n4) {
  int i = blockIdx.x * 256 + threadIdx.x;
  if (i < n4) {
    float4 v = *(const float4*)(s + 4 * (size_t)i);
    v.x = rnd_tf32(v.x); v.y = rnd_tf32(v.y);
    v.z = rnd_tf32(v.z); v.w = rnd_tf32(v.w);
    *(float4*)(d + 4 * (size_t)i) = v;
  }
}

// ---------------- GEMM via tf32 tensor cores (operands pre-rounded) ----------------
// MODE 0: C[row][col] = acc + bias (fp32)
// MODE 1: V-transposed store: C[col][jperm(row)] = tf32(acc + bias)
#define BM 128
#define BN 128
#define BK 32
#define AST 36
#define BST 136
#define GEMM_SMEM ((2 * (BM * AST + BK * BST)) * 4)

template <int MODE>
__global__ __launch_bounds__(256) void gemm_tc(
    const float* __restrict__ A, const float* __restrict__ W,
    const float* __restrict__ bias, float* __restrict__ C,
    int M, int N, int K) {
  extern __shared__ float smn[];
  float* As = smn;
  float* Bs = smn + 2 * BM * AST;

  const int t = threadIdx.x;
  const int m0 = blockIdx.y * BM;
  const int n0 = blockIdx.x * BN;
  const int warp = t >> 5, lane = t & 31;
  const int wm = (warp & 3) * 32;
  const int wn = (warp >> 2) * 64;
  const int g = lane >> 2, t4 = lane & 3;

  float c[2][8][4];
#pragma unroll
  for (int i = 0; i < 2; i++)
#pragma unroll
    for (int j = 0; j < 8; j++)
#pragma unroll
      for (int r = 0; r < 4; r++) c[i][j][r] = 0.f;

  auto prefetch = [&](int buf, int k0) {
    float* asb = As + buf * BM * AST;
    float* bsb = Bs + buf * BK * BST;
#pragma unroll
    for (int i = 0; i < 4; i++) {
      int idx = t + 256 * i;
      int row = idx >> 3, c4 = (idx & 7) << 2;
      int gr = m0 + row;
      if (gr >= M) gr = M - 1;
      unsigned dst = (unsigned)__cvta_generic_to_shared(asb + row * AST + c4);
      asm volatile("cp.async.cg.shared.global [%0], [%1], 16;" ::"r"(dst),
                   "l"(A + (size_t)gr * K + k0 + c4));
    }
#pragma unroll
    for (int i = 0; i < 4; i++) {
      int idx = t + 256 * i;
      int row = idx >> 5, c4 = (idx & 31) << 2;
      unsigned dst = (unsigned)__cvta_generic_to_shared(bsb + row * BST + c4);
      asm volatile("cp.async.cg.shared.global [%0], [%1], 16;" ::"r"(dst),
                   "l"(W + (size_t)(k0 + row) * N + n0 + c4));
    }
  };

  prefetch(0, 0);
  asm volatile("cp.async.commit_group;");

  const int KT = K / BK;
  for (int kt = 0; kt < KT; kt++) {
    const int buf = kt & 1;
    if (kt + 1 < KT) prefetch(buf ^ 1, (kt + 1) * BK);
    asm volatile("cp.async.commit_group;");
    asm volatile("cp.async.wait_group 1;");
    __syncthreads();

    const float* asb = As + buf * BM * AST;
    const float* bsb = Bs + buf * BK * BST;

#pragma unroll
    for (int ka = 0; ka < 4; ka++) {
      const int kk = ka * 8;
      unsigned av[2][4], bv[8][2];
#pragma unroll
      for (int am = 0; am < 2; am++) {
        const int r = wm + 16 * am + g;
        av[am][0] = __float_as_uint(asb[r * AST + kk + t4]);
        av[am][1] = __float_as_uint(asb[(r + 8) * AST + kk + t4]);
        av[am][2] = __float_as_uint(asb[r * AST + kk + t4 + 4]);
        av[am][3] = __float_as_uint(asb[(r + 8) * AST + kk + t4 + 4]);
      }
#pragma unroll
      for (int an = 0; an < 8; an++) {
        const int cn = wn + 8 * an + g;
        bv[an][0] = __float_as_uint(bsb[(kk + t4) * BST + cn]);
        bv[an][1] = __float_as_uint(bsb[(kk + t4 + 4) * BST + cn]);
      }
#pragma unroll
      for (int am = 0; am < 2; am++)
#pragma unroll
        for (int an = 0; an < 8; an++) mma_tf32(c[am][an], av[am], bv[an]);
    }
    __syncthreads();
  }

#pragma unroll
  for (int am = 0; am < 2; am++) {
    const int r0 = m0 + wm + 16 * am + g;
    const int r1 = r0 + 8;
#pragma unroll
    for (int an = 0; an < 8; an++) {
      const int col = n0 + wn + 8 * an + 2 * t4;
      const float b0 = bias[col], b1 = bias[col + 1];
      if (MODE == 0) {
        if (r0 < M) {
          float2 v0 = make_float2(c[am][an][0] + b0, c[am][an][1] + b1);
          *(float2*)(C + (size_t)r0 * N + col) = v0;
        }
        if (r1 < M) {
          float2 v1 = make_float2(c[am][an][2] + b0, c[am][an][3] + b1);
          *(float2*)(C + (size_t)r1 * N + col) = v1;
        }
      } else {
        if (r0 < M) {
          int jp = (r0 & ~7) | perm8(r0 & 7);
          C[(size_t)col * L_TOK + jp] = rnd_tf32(c[am][an][0] + b0);
          C[(size_t)(col + 1) * L_TOK + jp] = rnd_tf32(c[am][an][1] + b1);
        }
        if (r1 < M) {
          int jp = (r1 & ~7) | perm8(r1 & 7);
          C[(size_t)col * L_TOK + jp] = rnd_tf32(c[am][an][2] + b0);
          C[(size_t)(col + 1) * L_TOK + jp] = rnd_tf32(c[am][an][3] + b1);
        }
      }
    }
  }
}

// ---------------- fused RMSNorm + RoPE + tf32 round + k-perm store ----------------
__global__ __launch_bounds__(256) void rms_rope_kernel(
    float* __restrict__ qbuf, float* __restrict__ kbuf,
    const float* __restrict__ gq, const float* __restrict__ gk,
    const float* __restrict__ cosp, const float* __restrict__ sinp) {
  const int l = blockIdx.x;
  float* row = (blockIdx.y == 0) ? (qbuf + (size_t)l * DIM) : (kbuf + (size_t)l * DIM);
  const float* g = (blockIdx.y == 0) ? gq : gk;
  const int t = threadIdx.x;

  float2 v[3];
  float ss = 0.f;
#pragma unroll
  for (int j = 0; j < 3; j++) {
    int p = t + 256 * j;
    v[j] = ((const float2*)row)[p];
    ss += v[j].x * v[j].x + v[j].y * v[j].y;
  }
#pragma unroll
  for (int off = 16; off > 0; off >>= 1)
    ss += __shfl_xor_sync(0xffffffffu, ss, off);
  __shared__ float red[8];
  if ((t & 31) == 0) red[t >> 5] = ss;
  __syncthreads();
  float tot = 0.f;
#pragma unroll
  for (int w = 0; w < 8; w++) tot += red[w];
  const float r = rsqrtf(tot * (1.0f / (float)DIM) + 1e-6f);

#pragma unroll
  for (int j = 0; j < 3; j++) {
    int p = t + 256 * j;
    int hd2 = p & 63;
    float cth = cosp[l * 64 + hd2];
    float sth = sinp[l * 64 + hd2];
    float e = v[j].x * r * g[2 * p];
    float o = v[j].y * r * g[2 * p + 1];
    int d0 = 2 * p;
    int base = d0 & ~7;
    int m0 = d0 & 7;                       // even
    row[base + perm8(m0)] = rnd_tf32(e * cth - o * sth);
    row[base + perm8(m0 + 1)] = rnd_tf32(e * sth + o * cth);
  }
}

// ---------------- tensor-core flash attention ----------------
// 128 threads = 4 warps, 2x2 (rows x cols/d). BQ=BKV=64.
// Qs[64][132], KV union (K[64][132] / Vt[128][68]), Ps[64][68].
#define ATT_SMEM_F (8448 + 8704 + 4352 + 64 + 64 + 128 + 128)
#define ATT_SMEM (ATT_SMEM_F * 4)

__global__ __launch_bounds__(128, 2) void attn_tc_kernel(
    const float* __restrict__ q, const float* __restrict__ k,
    const float* __restrict__ vt, float* __restrict__ o) {
  extern __shared__ float sm[];
  float* Qs = sm;                 // [64][132]
  float* KVs = sm + 8448;         // K [64][132] then Vt [128][68]
  float* Ps = KVs + 8704;         // [64][68]
  float* m_s = Ps + 4352;         // [64]
  float* l_s = m_s + 64;          // [64]
  float* red_m = l_s + 64;        // [64][2]
  float* red_l = red_m + 128;     // [64][2]

  const int t = threadIdx.x, lane = t & 31, warp = t >> 5;
  const int g = lane >> 2, t4 = lane & 3;
  const int wr = warp & 1, wc = warp >> 1;
  const int q0 = blockIdx.x * 64, h = blockIdx.y;
  const int r0l = wr * 32 + g;    // local row for (m=0,hf=0)

  // ---- Q tile (pure cp.async; data pre-rounded & k-permuted) ----
#pragma unroll
  for (int i = 0; i < 16; i++) {
    int idx = t + 128 * i, r = idx >> 5, c4 = (idx & 31) << 2;
    int qr = q0 + r;
    int sz = (qr < L_TOK) ? 16 : 0;
    if (qr >= L_TOK) qr = L_TOK - 1;
    unsigned dst = (unsigned)__cvta_generic_to_shared(Qs + r * 132 + c4);
    asm volatile("cp.async.cg.shared.global [%0], [%1], 16, %2;" ::"r"(dst),
                 "l"(q + (size_t)qr * DIM + h * HD + c4), "r"(sz));
  }
  asm volatile("cp.async.commit_group;");
  if (t < 64) { m_s[t] = -3.0e38f; l_s[t] = 0.f; }

  float oa[2][8][4];
#pragma unroll
  for (int m = 0; m < 2; m++)
#pragma unroll
    for (int a = 0; a < 8; a++)
#pragma unroll
      for (int r = 0; r < 4; r++) oa[m][a][r] = 0.f;

  int km[2][2];
#pragma unroll
  for (int m = 0; m < 2; m++)
#pragma unroll
    for (int hf = 0; hf < 2; hf++) {
      int grow = q0 + r0l + 16 * m + 8 * hf;
      km[m][hf] = (grow < FR) ? FR : L_TOK;
    }

  int qlast = q0 + 63; if (qlast >= L_TOK) qlast = L_TOK - 1;
  const int ntiles = (((qlast < FR) ? FR : L_TOK) + 63) >> 6;

  for (int kt = 0; kt < ntiles; kt++) {
    const int kb = kt * 64;
    __syncthreads();                                   // A: prev PV done
    // ---- K tile ----
#pragma unroll
    for (int i = 0; i < 16; i++) {
      int idx = t + 128 * i, r = idx >> 5, c4 = (idx & 31) << 2;
      int kr = kb + r;
      int sz = (kr < L_TOK) ? 16 : 0;
      if (kr >= L_TOK) kr = L_TOK - 1;
      unsigned dst = (unsigned)__cvta_generic_to_shared(KVs + r * 132 + c4);
      asm volatile("cp.async.cg.shared.global [%0], [%1], 16, %2;" ::"r"(dst),
                   "l"(k + (size_t)kr * DIM + h * HD + c4), "r"(sz));
    }
    asm volatile("cp.async.commit_group;");
    asm volatile("cp.async.wait_group 0;");
    __syncthreads();                                   // B

    // ---- S = Q K^T ----
    float s_[2][4][4];
#pragma unroll
    for (int m = 0; m < 2; m++)
#pragma unroll
      for (int a = 0; a < 4; a++)
#pragma unroll
        for (int r = 0; r < 4; r++) s_[m][a][r] = 0.f;

#pragma unroll
    for (int k8 = 0; k8 < 16; k8++) {
      unsigned av[2][4];
#pragma unroll
      for (int m = 0; m < 2; m++) {
        float2 x0 = *(const float2*)(Qs + (wr * 32 + m * 16 + g) * 132 + k8 * 8 + 2 * t4);
        float2 x1 = *(const float2*)(Qs + (wr * 32 + m * 16 + g + 8) * 132 + k8 * 8 + 2 * t4);
        av[m][0] = __float_as_uint(x0.x); av[m][1] = __float_as_uint(x1.x);
        av[m][2] = __float_as_uint(x0.y); av[m][3] = __float_as_uint(x1.y);
      }
#pragma unroll
      for (int a = 0; a < 4; a++) {
        float2 kv = *(const float2*)(KVs + (wc * 32 + a * 8 + g) * 132 + k8 * 8 + 2 * t4);
        unsigned bv[2] = {__float_as_uint(kv.x), __float_as_uint(kv.y)};
        mma_tf32(s_[0][a], av[0], bv);
        mma_tf32(s_[1][a], av[1], bv);
      }
    }

    // ---- scale + mask ----
#pragma unroll
    for (int m = 0; m < 2; m++)
#pragma unroll
      for (int a = 0; a < 4; a++) {
        int cb = kb + wc * 32 + a * 8 + 2 * t4;
        s_[m][a][0] = (cb     < km[m][0]) ? s_[m][a][0] * SCALE_F : -3.0e38f;
        s_[m][a][1] = (cb + 1 < km[m][0]) ? s_[m][a][1] * SCALE_F : -3.0e38f;
        s_[m][a][2] = (cb     < km[m][1]) ? s_[m][a][2] * SCALE_F : -3.0e38f;
        s_[m][a][3] = (cb + 1 < km[m][1]) ? s_[m][a][3] * SCALE_F : -3.0e38f;
      }

    // ---- partial row max -> smem ----
    float pm[2][2];
#pragma unroll
    for (int m = 0; m < 2; m++) { pm[m][0] = -3.0e38f; pm[m][1] = -3.0e38f; }
#pragma unroll
    for (int m = 0; m < 2; m++)
#pragma unroll
      for (int a = 0; a < 4; a++) {
        pm[m][0] = fmaxf(pm[m][0], fmaxf(s_[m][a][0], s_[m][a][1]));
        pm[m][1] = fmaxf(pm[m][1], fmaxf(s_[m][a][2], s_[m][a][3]));
      }
#pragma unroll
    for (int m = 0; m < 2; m++)
#pragma unroll
      for (int hf = 0; hf < 2; hf++) {
        pm[m][hf] = fmaxf(pm[m][hf], __shfl_xor_sync(0xffffffffu, pm[m][hf], 1));
        pm[m][hf] = fmaxf(pm[m][hf], __shfl_xor_sync(0xffffffffu, pm[m][hf], 2));
      }
    if (t4 == 0) {
#pragma unroll
      for (int m = 0; m < 2; m++)
#pragma unroll
        for (int hf = 0; hf < 2; hf++)
          red_m[(r0l + 16 * m + 8 * hf) * 2 + wc] = pm[m][hf];
    }
    __syncthreads();                                   // C (K reads done)

    // ---- V tile (overwrites K region; Vt layout [128 d][64 j]) ----
#pragma unroll
    for (int i = 0; i < 16; i++) {
      int idx = t + 128 * i, d = idx >> 4, cq = (idx & 15) << 2;
      int jj = kb + cq;
      int sz = (jj < L_TOK) ? 16 : 0;
      if (jj >= L_TOK) jj = L_TOK - 4;
      unsigned dst = (unsigned)__cvta_generic_to_shared(KVs + d * 68 + cq);
      asm volatile("cp.async.cg.shared.global [%0], [%1], 16, %2;" ::"r"(dst),
                   "l"(vt + (size_t)(h * HD + d) * L_TOK + jj), "r"(sz));
    }
    asm volatile("cp.async.commit_group;");

    // ---- softmax ----
    float mnew[2][2], corr[2][2];
#pragma unroll
    for (int m = 0; m < 2; m++)
#pragma unroll
      for (int hf = 0; hf < 2; hf++) {
        int rl = r0l + 16 * m + 8 * hf;
        float mold = m_s[rl];
        float mn = fmaxf(mold, fmaxf(red_m[rl * 2], red_m[rl * 2 + 1]));
        mnew[m][hf] = mn;
        corr[m][hf] = __expf(mold - mn);
      }
    float pl[2][2] = {{0.f, 0.f}, {0.f, 0.f}};
    const int p0pos = (t4 < 2) ? 4 * t4 : 4 * t4 - 7;       // perm of 2*t4
    const int p1pos = (t4 < 2) ? 4 * t4 + 2 : 4 * t4 - 5;   // perm of 2*t4+1
#pragma unroll
    for (int m = 0; m < 2; m++) {
      int rl0 = r0l + 16 * m;
#pragma unroll
      for (int a = 0; a < 4; a++) {
        int cp0 = wc * 32 + a * 8;
        float e0 = __expf(s_[m][a][0] - mnew[m][0]);
        float e1 = __expf(s_[m][a][1] - mnew[m][0]);
        float e2 = __expf(s_[m][a][2] - mnew[m][1]);
        float e3 = __expf(s_[m][a][3] - mnew[m][1]);
        pl[m][0] += e0 + e1;
        pl[m][1] += e2 + e3;
        Ps[rl0 * 68 + cp0 + p0pos] = rnd_tf32(e0);
        Ps[rl0 * 68 + cp0 + p1pos] = rnd_tf32(e1);
        Ps[(rl0 + 8) * 68 + cp0 + p0pos] = rnd_tf32(e2);
        Ps[(rl0 + 8) * 68 + cp0 + p1pos] = rnd_tf32(e3);
      }
    }
#pragma unroll
    for (int m = 0; m < 2; m++)
#pragma unroll
      for (int hf = 0; hf < 2; hf++) {
        pl[m][hf] += __shfl_xor_sync(0xffffffffu, pl[m][hf], 1);
        pl[m][hf] += __shfl_xor_sync(0xffffffffu, pl[m][hf], 2);
      }
    if (t4 == 0) {
#pragma unroll
      for (int m = 0; m < 2; m++)
#pragma unroll
        for (int hf = 0; hf < 2; hf++)
          red_l[(r0l + 16 * m + 8 * hf) * 2 + wc] = pl[m][hf];
    }
    __syncthreads();                                   // D
    if (wc == 0 && t4 == 0) {
#pragma unroll
      for (int m = 0; m < 2; m++)
#pragma unroll
        for (int hf = 0; hf < 2; hf++) {
          int rl = r0l + 16 * m + 8 * hf;
          l_s[rl] = l_s[rl] * corr[m][hf] + red_l[rl * 2] + red_l[rl * 2 + 1];
          m_s[rl] = mnew[m][hf];
        }
    }
    // rescale O accumulators
#pragma unroll
    for (int m = 0; m < 2; m++)
#pragma unroll
      for (int a = 0; a < 8; a++) {
        oa[m][a][0] *= corr[m][0]; oa[m][a][1] *= corr[m][0];
        oa[m][a][2] *= corr[m][1]; oa[m][a][3] *= corr[m][1];
      }
    asm volatile("cp.async.wait_group 0;");
    __syncthreads();                                   // E: V ready, Ps visible

    // ---- O += P V ----
#pragma unroll
    for (int k8 = 0; k8 < 8; k8++) {
      unsigned av[2][4];
#pragma unroll
      for (int m = 0; m < 2; m++) {
        float2 p0 = *(const float2*)(Ps + (wr * 32 + 16 * m + g) * 68 + k8 * 8 + 2 * t4);
        float2 p1 = *(const float2*)(Ps + (wr * 32 + 16 * m + g + 8) * 68 + k8 * 8 + 2 * t4);
        av[m][0] = __float_as_uint(p0.x); av[m][1] = __float_as_uint(p1.x);
        av[m][2] = __float_as_uint(p0.y); av[m][3] = __float_as_uint(p1.y);
      }
#pragma unroll
      for (int a = 0; a < 8; a++) {
        float2 vv = *(const float2*)(KVs + (wc * 64 + a * 8 + g) * 68 + k8 * 8 + 2 * t4);
        unsigned bv[2] = {__float_as_uint(vv.x), __float_as_uint(vv.y)};
        mma_tf32(oa[0][a], av[0], bv);
        mma_tf32(oa[1][a], av[1], bv);
      }
    }
  }
  __syncthreads();

  // ---- epilogue: /l, round to tf32 (feeds O-projection GEMM) ----
#pragma unroll
  for (int m = 0; m < 2; m++)
#pragma unroll
    for (int hf = 0; hf < 2; hf++) {
      int rl = r0l + 16 * m + 8 * hf;
      int grow = q0 + rl;
      if (grow < L_TOK) {
        float inv = 1.0f / l_s[rl];
#pragma unroll
        for (int a = 0; a < 8; a++) {
          int col = h * HD + wc * 64 + a * 8 + 2 * t4;
          float2 w;
          w.x = rnd_tf32(oa[m][a][hf * 2] * inv);
          w.y = rnd_tf32(oa[m][a][hf * 2 + 1] * inv);
          *(float2*)(o + (size_t)grow * DIM + col) = w;
        }
      }
    }
}

// ---------------- launch ----------------
extern "C" void kernel_launch(void* const* d_in, const int* in_sizes, int n_in,
                              void* d_out, int out_size) {
  const float* x  = (const float*)d_in[0];
  const float* wq = (const float*)d_in[1];
  const float* wk = (const float*)d_in[2];
  const float* wv = (const float*)d_in[3];
  const float* wo = (const float*)d_in[4];
  const float* bq = (const float*)d_in[5];
  const float* bk = (const float*)d_in[6];
  const float* bv = (const float*)d_in[7];
  const float* bo = (const float*)d_in[8];
  const float* gq = (const float*)d_in[9];
  const float* gk = (const float*)d_in[10];
  const float* fc = (const float*)d_in[11];
  const float* fs = (const float*)d_in[12];
  float* out = (float*)d_out;

  float *qb, *kb, *vb, *ab, *xt, *wt;
  cudaGetSymbolAddress((void**)&qb, g_q);
  cudaGetSymbolAddress((void**)&kb, g_k);
  cudaGetSymbolAddress((void**)&vb, g_v);
  cudaGetSymbolAddress((void**)&ab, g_a);
  cudaGetSymbolAddress((void**)&xt, g_xt);
  cudaGetSymbolAddress((void**)&wt, g_wt);
  float* wqt = wt;
  float* wkt = wt + (size_t)DIM * DIM;
  float* wvt = wt + 2 * (size_t)DIM * DIM;
  float* wot = wt + 3 * (size_t)DIM * DIM;

  cudaFuncSetAttribute(gemm_tc<0>, cudaFuncAttributeMaxDynamicSharedMemorySize, GEMM_SMEM);
  cudaFuncSetAttribute(gemm_tc<1>, cudaFuncAttributeMaxDynamicSharedMemorySize, GEMM_SMEM);
  cudaFuncSetAttribute(attn_tc_kernel, cudaFuncAttributeMaxDynamicSharedMemorySize, ATT_SMEM);

  // pre-round operands to tf32
  int nx4 = L_TOK * DIM / 4, nw4 = DIM * DIM / 4;
  cvt_kernel<<<(nx4 + 255) / 256, 256>>>(x, xt, nx4);
  cvt_kernel<<<(nw4 + 255) / 256, 256>>>(wq, wqt, nw4);
  cvt_kernel<<<(nw4 + 255) / 256, 256>>>(wk, wkt, nw4);
  cvt_kernel<<<(nw4 + 255) / 256, 256>>>(wv, wvt, nw4);
  cvt_kernel<<<(nw4 + 255) / 256, 256>>>(wo, wot, nw4);

  dim3 gg(DIM / 128, (L_TOK + 127) / 128);
  gemm_tc<0><<<gg, 256, GEMM_SMEM>>>(xt, wqt, bq, qb, L_TOK, DIM, DIM);
  gemm_tc<0><<<gg, 256, GEMM_SMEM>>>(xt, wkt, bk, kb, L_TOK, DIM, DIM);
  gemm_tc<1><<<gg, 256, GEMM_SMEM>>>(xt, wvt, bv, vb, L_TOK, DIM, DIM);

  rms_rope_kernel<<<dim3(L_TOK, 2), 256>>>(qb, kb, gq, gk, fc, fs);

  attn_tc_kernel<<<dim3((L_TOK + 63) / 64, NH), 128, ATT_SMEM>>>(qb, kb, vb, ab);

  gemm_tc<0><<<gg, 256, GEMM_SMEM>>>(ab, wot, bo, out, L_TOK, DIM, DIM);
}